// round 15
// baseline (speedup 1.0000x reference)
#include <cuda_runtime.h>

#define POOLK 7
#define NBINS (POOLK * POOLK)
#define NUM_ROIS 300
#define FH 50
#define FW 50
#define FC 512
#define NPIX (FH * FW)
#define NBIN_TOT (NUM_ROIS * NBINS)   // 14700
#define CTAS 592                       // 4/SM even at 1024 thr/SM: no deadlock
#define THREADS 256
#define WARPS (CTAS * (THREADS / 32))  // 4736
// bins per CTA: first 492 CTAs get 25, remaining 100 get 24 (14700 total)
#define SPLIT 492

// Scratch + barrier state (no cudaMalloc allowed; zero-initialized)
__device__ float g_fmax[NPIX];
__device__ unsigned g_ctr = 0;
__device__ volatile unsigned g_gen = 0;

__global__ void __launch_bounds__(THREADS) fused_kernel(
    const float* __restrict__ rois,
    const float* __restrict__ fm,
    float* __restrict__ out)
{
    __shared__ float sbin[25];
    int tid = threadIdx.x;
    int lane = tid & 31;
    int gwarp = blockIdx.x * (THREADS / 32) + (tid >> 5);

    // ---- Phase 1: channel-max per pixel, warp-per-pixel (4736 warps) ----
    for (int pix = gwarp; pix < NPIX; pix += WARPS) {
        const float4* p = reinterpret_cast<const float4*>(fm + (size_t)pix * FC);
        float m = -INFINITY;
#pragma unroll
        for (int k = 0; k < 4; k++) {
            float4 v = p[lane + 32 * k];
            m = fmaxf(m, fmaxf(fmaxf(v.x, v.y), fmaxf(v.z, v.w)));
        }
#pragma unroll
        for (int off = 16; off > 0; off >>= 1)
            m = fmaxf(m, __shfl_xor_sync(0xffffffffu, m, off));
        if (lane == 0) g_fmax[pix] = m;
    }
    __syncthreads();

    // ---- Grid barrier (replay-safe: g_gen monotone, g_ctr resets) ----
    if (tid == 0) {
        __threadfence();                        // publish g_fmax
        unsigned g = g_gen;
        if (atomicAdd(&g_ctr, 1u) == CTAS - 1) {
            g_ctr = 0;
            __threadfence();
            g_gen = g + 1;                      // release
        } else {
            while (g_gen == g) __nanosleep(64);
            __threadfence();                    // acquire
        }
    }
    __syncthreads();

    // ---- Phase 2: CTA-local binmax + slab write ----
    int c = blockIdx.x;
    int nb = (c < SPLIT) ? 25 : 24;
    int lo = 24 * c + min(c, SPLIT);            // first bin of this CTA

    if (tid < nb) {
        int idx = lo + tid;
        int r = idx / NBINS;
        int bin = idx - r * NBINS;
        int i = bin / POOLK;
        int j = bin - i * POOLK;

        const float* roi = rois + r * 5;
        // reference: (rois * (1/16)).astype(int32) -> truncation; inputs >= 0
        int x1 = (int)(__ldg(roi + 1) * 0.0625f);
        int y1 = (int)(__ldg(roi + 2) * 0.0625f);
        int x2 = (int)(__ldg(roi + 3) * 0.0625f);
        int y2 = (int)(__ldg(roi + 4) * 0.0625f);
        int rh = y2 - y1 + 1;
        int rw = x2 - x1 + 1;

        int hs = min(max(y1 + (i * rh) / POOLK, 0), FH);
        int he = min(max(y1 + ((i + 1) * rh + POOLK - 1) / POOLK, 0), FH);
        int ws = min(max(x1 + (j * rw) / POOLK, 0), FW);
        int we = min(max(x1 + ((j + 1) * rw + POOLK - 1) / POOLK, 0), FW);

        float m = -INFINITY;
        for (int y = hs; y < he; y++) {
            const float* row = g_fmax + y * FW;
#pragma unroll 8
            for (int x = ws; x < we; x++)
                m = fmaxf(m, __ldcg(row + x));  // L2-fresh (skip L1)
        }
        sbin[tid] = m;
    }
    __syncthreads();

    // Interleaved coalesced write: k>>7 warp-uniform -> LDS broadcast,
    // STG.128 fully coalesced across the CTA's contiguous slab.
    float4* o = reinterpret_cast<float4*>(out) + (size_t)lo * (FC / 4);
    int total = nb * (FC / 4);                  // 3072 or 3200 f4
    for (int k = tid; k < total; k += THREADS) {
        float v = sbin[k >> 7];
        o[k] = make_float4(v, v, v, v);
    }
}

extern "C" void kernel_launch(void* const* d_in, const int* in_sizes, int n_in,
                              void* d_out, int out_size) {
    const float* rois = (const float*)d_in[0];          // (300, 5)
    const float* feature_maps = (const float*)d_in[1];  // (50, 50, 512)
    float* out = (float*)d_out;                         // (300, 7, 7, 512)

    fused_kernel<<<CTAS, THREADS>>>(rois, feature_maps, out);
}

// round 16
// speedup vs baseline: 1.2857x; 1.2857x over previous
#include <cuda_runtime.h>
#include <cstdint>

#define POOLK 7
#define NBINS (POOLK * POOLK)
#define NUM_ROIS 300
#define FH 50
#define FW 50
#define FC 512
#define NPIX (FH * FW)
#define NBIN_TOT (NUM_ROIS * NBINS)   // 14700
#define BPB 10                         // bins per slab
#define NSLAB (NBIN_TOT / BPB)         // 1470
#define SLAB_F4 (BPB * FC / 4)         // 1280 float4 = 20 KB
#define SLAB_BYTES (SLAB_F4 * 16)      // 20480
#define K2_CTAS 296                    // 2 per SM, persistent

// Scratch (no cudaMalloc allowed)
__device__ float g_fmax[NPIX];

__device__ __forceinline__ uint32_t smem_u32(const void* p) {
    uint32_t a;
    asm("{ .reg .u64 t; cvta.to.shared.u64 t, %1; cvt.u32.u64 %0, t; }"
        : "=r"(a) : "l"(p));
    return a;
}

// K1: one warp per pixel, channel-max over 512 floats (MLP=4/thread).
__global__ void fmax_kernel(const float* __restrict__ fm) {
    int warp = (blockIdx.x * blockDim.x + threadIdx.x) >> 5;
    int lane = threadIdx.x & 31;
    if (warp >= NPIX) return;
    const float4* p = reinterpret_cast<const float4*>(fm + (size_t)warp * FC);
    float m = -INFINITY;
#pragma unroll
    for (int k = 0; k < 4; k++) {
        float4 v = p[lane + 32 * k];
        m = fmaxf(m, fmaxf(fmaxf(v.x, v.y), fmaxf(v.z, v.w)));
    }
#pragma unroll
    for (int off = 16; off > 0; off >>= 1)
        m = fmaxf(m, __shfl_xor_sync(0xffffffffu, m, off));
    if (lane == 0) g_fmax[warp] = m;
}

// K2: persistent double-buffered TMA writer. 296 CTAs loop over 1470 slabs
// of 10 bins (20 KB each). Bulk stores are committed WITHOUT waiting; the
// drain of slab i overlaps binmax+build of slab i+1. wait_group 1 gates
// buffer reuse (the store issued two iterations ago).
__global__ void __launch_bounds__(256) roi_pipe_kernel(
    const float* __restrict__ rois, float* __restrict__ out) {
    __shared__ float4 buf[2][SLAB_F4];        // 2 x 20 KB
    __shared__ float sbin[2][BPB];
    int tid = threadIdx.x;

    int it = 0;
    for (int s = blockIdx.x; s < NSLAB; s += gridDim.x, ++it) {
        int p = it & 1;

        // Free buffer p: at most 1 bulk group may remain in flight.
        if (tid == 0)
            asm volatile("cp.async.bulk.wait_group 1;" ::: "memory");
        __syncthreads();

        // Phase A: 16 threads per bin (threads 0..159).
        if (tid < BPB * 16) {
            int b = tid >> 4;
            int sub = tid & 15;
            int idx = s * BPB + b;
            int r = idx / NBINS;
            int bin = idx - r * NBINS;
            int i = bin / POOLK;
            int j = bin - i * POOLK;

            const float* roi = rois + r * 5;
            // reference: (rois*(1/16)).astype(int32) -> truncation; inputs>=0
            int x1 = (int)(__ldg(roi + 1) * 0.0625f);
            int y1 = (int)(__ldg(roi + 2) * 0.0625f);
            int x2 = (int)(__ldg(roi + 3) * 0.0625f);
            int y2 = (int)(__ldg(roi + 4) * 0.0625f);
            int rh = y2 - y1 + 1;
            int rw = x2 - x1 + 1;

            int hs = min(max(y1 + (i * rh) / POOLK, 0), FH);
            int he = min(max(y1 + ((i + 1) * rh + POOLK - 1) / POOLK, 0), FH);
            int ws = min(max(x1 + (j * rw) / POOLK, 0), FW);
            int we = min(max(x1 + ((j + 1) * rw + POOLK - 1) / POOLK, 0), FW);

            int nh = he - hs;
            int nw = we - ws;
            int n = nh * nw;                   // <= 64

            float m = -INFINITY;
#pragma unroll 4
            for (int t = sub; t < n; t += 16) {
                int dy = t / nw;
                int dx = t - dy * nw;
                m = fmaxf(m, __ldg(g_fmax + (hs + dy) * FW + (ws + dx)));
            }
            // reduce across the 16-lane subgroup (stays inside one warp)
#pragma unroll
            for (int off = 8; off > 0; off >>= 1)
                m = fmaxf(m, __shfl_xor_sync(0xffffffffu, m, off));
            if (sub == 0) sbin[p][b] = m;
        }
        __syncthreads();

        // Build slab: k = i*256+tid, bin = k>>7 (warp-uniform broadcast).
#pragma unroll
        for (int i = 0; i < SLAB_F4 / 256; i++) {
            float v = sbin[p][(i * 256 + tid) >> 7];
            buf[p][i * 256 + tid] = make_float4(v, v, v, v);
        }
        __syncthreads();

        // Issue bulk store; do NOT wait — it drains under the next iteration.
        if (tid == 0) {
            asm volatile("fence.proxy.async.shared::cta;" ::: "memory");
            uint64_t gdst = (uint64_t)(out + (size_t)s * BPB * FC);
            uint32_t ssrc = smem_u32(buf[p]);
            asm volatile(
                "cp.async.bulk.global.shared::cta.bulk_group [%0], [%1], %2;"
                :: "l"(gdst), "r"(ssrc), "n"(SLAB_BYTES) : "memory");
            asm volatile("cp.async.bulk.commit_group;" ::: "memory");
        }
    }

    // Drain all outstanding stores before smem is deallocated.
    if (tid == 0)
        asm volatile("cp.async.bulk.wait_group 0;" ::: "memory");
    __syncthreads();
}

extern "C" void kernel_launch(void* const* d_in, const int* in_sizes, int n_in,
                              void* d_out, int out_size) {
    const float* rois = (const float*)d_in[0];          // (300, 5)
    const float* feature_maps = (const float*)d_in[1];  // (50, 50, 512)
    float* out = (float*)d_out;                         // (300, 7, 7, 512)

    fmax_kernel<<<(NPIX * 32 + 255) / 256, 256>>>(feature_maps);
    roi_pipe_kernel<<<K2_CTAS, 256>>>(rois, out);
}